// round 1
// baseline (speedup 1.0000x reference)
#include <cuda_runtime.h>
#include <math.h>

#define Kc 65536
#define Dc 256
#define Oc 256
#define Bc 1024
#define TOPK 32
#define TWOD 512

// Scratch (device globals: no runtime allocation allowed)
__device__ float g_w[(size_t)Kc * TWOD];        // 128 MB packed [mean*iv | iv]
__device__ float g_bias[Kc];
__device__ float g_xp[(size_t)Bc * TWOD];       // 2 MB packed [x | -0.5*x^2]
__device__ float g_logits[(size_t)Bc * Kc];     // 256 MB

__device__ __forceinline__ float neg_inf() { return __int_as_float(0xff800000); }

// ---------------- prep kernels ----------------
__global__ void prep_x_kernel(const float* __restrict__ x) {
    int b = blockIdx.x;
    int d = threadIdx.x;
    float v = x[b * Dc + d];
    g_xp[(size_t)b * TWOD + d]       = v;            // pairs with mean*iv
    g_xp[(size_t)b * TWOD + Dc + d]  = -0.5f * v * v; // pairs with iv
}

__global__ void prep_w_kernel(const float* __restrict__ mean,
                              const float* __restrict__ stddev) {
    int k = blockIdx.x;
    int d = threadIdx.x;
    float s  = stddev[(size_t)k * Dc + d];
    float m  = mean[(size_t)k * Dc + d];
    float iv = 1.0f / (s * s);
    g_w[(size_t)k * TWOD + d]      = m * iv;
    g_w[(size_t)k * TWOD + Dc + d] = iv;
    float part = -0.5f * m * m * iv - logf(s);
    __shared__ float red[256];
    red[d] = part;
    __syncthreads();
    #pragma unroll
    for (int off = 128; off > 0; off >>= 1) {
        if (d < off) red[d] += red[d + off];
        __syncthreads();
    }
    if (d == 0) {
        // 0.5 * D * ln(2*pi)
        g_bias[k] = red[0] - 0.5f * (float)Dc * 1.8378770664093453f;
    }
}

// ---------------- GEMM: logits = xp @ w^T + bias ----------------
#define BM 128
#define BN 128
#define BK 16
#define SSTR (BM + 4)   // 132, keeps float4 alignment per row

__global__ __launch_bounds__(256) void gemm_kernel() {
    __shared__ float As[BK][SSTR];
    __shared__ float Ws[BK][SSTR];

    int nb = blockIdx.x;  // k-tile (N dim)
    int mb = blockIdx.y;  // b-tile (M dim)
    int tid = threadIdx.x;
    int tx = tid & 15;    // 0..15 -> 8 cols each
    int ty = tid >> 4;    // 0..15 -> 8 rows each

    int rowL = tid >> 2;  // 0..63 for loading
    int jq   = tid & 3;   // 0..3  -> 4 consecutive j

    float acc[8][8];
    #pragma unroll
    for (int i = 0; i < 8; i++)
        #pragma unroll
        for (int j = 0; j < 8; j++) acc[i][j] = 0.0f;

    for (int j0 = 0; j0 < TWOD; j0 += BK) {
        #pragma unroll
        for (int h = 0; h < 2; h++) {
            int r = rowL + h * 64;
            float4 av = *(const float4*)&g_xp[(size_t)(mb * BM + r) * TWOD + j0 + jq * 4];
            As[jq * 4 + 0][r] = av.x;
            As[jq * 4 + 1][r] = av.y;
            As[jq * 4 + 2][r] = av.z;
            As[jq * 4 + 3][r] = av.w;
            float4 wv = *(const float4*)&g_w[(size_t)(nb * BN + r) * TWOD + j0 + jq * 4];
            Ws[jq * 4 + 0][r] = wv.x;
            Ws[jq * 4 + 1][r] = wv.y;
            Ws[jq * 4 + 2][r] = wv.z;
            Ws[jq * 4 + 3][r] = wv.w;
        }
        __syncthreads();

        #pragma unroll
        for (int jj = 0; jj < BK; jj++) {
            float4 a0 = *(const float4*)&As[jj][ty * 8];
            float4 a1 = *(const float4*)&As[jj][ty * 8 + 4];
            float4 w0 = *(const float4*)&Ws[jj][tx * 8];
            float4 w1 = *(const float4*)&Ws[jj][tx * 8 + 4];
            float a[8] = {a0.x, a0.y, a0.z, a0.w, a1.x, a1.y, a1.z, a1.w};
            float w[8] = {w0.x, w0.y, w0.z, w0.w, w1.x, w1.y, w1.z, w1.w};
            #pragma unroll
            for (int i = 0; i < 8; i++)
                #pragma unroll
                for (int j = 0; j < 8; j++)
                    acc[i][j] += a[i] * w[j];
        }
        __syncthreads();
    }

    int gr = mb * BM + ty * 8;
    int gc = nb * BN + tx * 8;
    float b4a[4], b4b[4];
    {
        float4 t0 = *(const float4*)&g_bias[gc];
        float4 t1 = *(const float4*)&g_bias[gc + 4];
        b4a[0] = t0.x; b4a[1] = t0.y; b4a[2] = t0.z; b4a[3] = t0.w;
        b4b[0] = t1.x; b4b[1] = t1.y; b4b[2] = t1.z; b4b[3] = t1.w;
    }
    #pragma unroll
    for (int i = 0; i < 8; i++) {
        float4 o0 = make_float4(acc[i][0] + b4a[0], acc[i][1] + b4a[1],
                                acc[i][2] + b4a[2], acc[i][3] + b4a[3]);
        float4 o1 = make_float4(acc[i][4] + b4b[0], acc[i][5] + b4b[1],
                                acc[i][6] + b4b[2], acc[i][7] + b4b[3]);
        float* dst = &g_logits[(size_t)(gr + i) * Kc + gc];
        *(float4*)dst       = o0;
        *(float4*)(dst + 4) = o1;
    }
}

// ---------------- top-k + softmax + gather ----------------
__global__ __launch_bounds__(1024) void topk_kernel(const float* __restrict__ outputs,
                                                    float* __restrict__ out) {
    int b = blockIdx.x;
    int t = threadIdx.x;
    float* row = &g_logits[(size_t)b * Kc];

    const float NI = neg_inf();
    float v[8];
    int   id[8];
    #pragma unroll
    for (int i = 0; i < 8; i++) { v[i] = NI; id[i] = -1; }

    // initial scan: thread t owns indices t + 1024*j (coalesced)
    for (int j = 0; j < 64; j++) {
        int k = t + (j << 10);
        float val = row[k];
        if (val > v[7]) {
            v[7] = val; id[7] = k;
            #pragma unroll
            for (int i = 7; i > 0; --i) {
                if (v[i] > v[i - 1]) {
                    float tv = v[i]; v[i] = v[i - 1]; v[i - 1] = tv;
                    int ti = id[i]; id[i] = id[i - 1]; id[i - 1] = ti;
                }
            }
        }
    }

    __shared__ float swv[32];
    __shared__ int   swi[32];
    __shared__ float s_curv;
    __shared__ int   s_curi;
    __shared__ float sel_val[TOPK];
    __shared__ int   sel_idx[TOPK];
    __shared__ float s_w[TOPK];
    __shared__ float part[4 * 256];

    int lane = t & 31, warp = t >> 5;

    for (int r = 0; r < TOPK; r++) {
        float bv = v[0];
        int   bi = id[0];
        #pragma unroll
        for (int off = 16; off > 0; off >>= 1) {
            float ov = __shfl_down_sync(0xffffffffu, bv, off);
            int   oi = __shfl_down_sync(0xffffffffu, bi, off);
            if (ov > bv) { bv = ov; bi = oi; }
        }
        if (lane == 0) { swv[warp] = bv; swi[warp] = bi; }
        __syncthreads();
        if (warp == 0) {
            bv = swv[lane]; bi = swi[lane];
            #pragma unroll
            for (int off = 16; off > 0; off >>= 1) {
                float ov = __shfl_down_sync(0xffffffffu, bv, off);
                int   oi = __shfl_down_sync(0xffffffffu, bi, off);
                if (ov > bv) { bv = ov; bi = oi; }
            }
            if (lane == 0) {
                s_curv = bv; s_curi = bi;
                sel_val[r] = bv; sel_idx[r] = bi;
            }
        }
        __syncthreads();
        int ci = s_curi;
        if ((ci & 1023) == t) {
            // pop my best
            #pragma unroll
            for (int i = 0; i < 7; i++) { v[i] = v[i + 1]; id[i] = id[i + 1]; }
            v[7] = NI; id[7] = -1;
            row[ci] = NI;  // mark consumed (logits regenerated each launch)
            if (v[0] == NI) {
                // exhausted local heap (astronomically rare) -> exact rescan
                for (int j = 0; j < 64; j++) {
                    int k = t + (j << 10);
                    float val = row[k];   // consumed entries already -inf
                    if (val > v[7]) {
                        v[7] = val; id[7] = k;
                        #pragma unroll
                        for (int i = 7; i > 0; --i) {
                            if (v[i] > v[i - 1]) {
                                float tv = v[i]; v[i] = v[i - 1]; v[i - 1] = tv;
                                int ti = id[i]; id[i] = id[i - 1]; id[i - 1] = ti;
                            }
                        }
                    }
                }
            }
        }
    }
    __syncthreads();

    // softmax over the 32 selected (sel_val[0] is the max: extracted descending)
    if (t < 32) {
        float e = expf(sel_val[t] - sel_val[0]);
        float s = e;
        #pragma unroll
        for (int off = 16; off > 0; off >>= 1)
            s += __shfl_xor_sync(0xffffffffu, s, off);
        s_w[t] = e / s;
    }
    __syncthreads();

    // weighted gather-sum: out[b, :] = sum_j w[j] * outputs[sel_idx[j], :]
    int o = t & 255;
    int g = t >> 8;   // 0..3, each handles 8 of 32
    float p = 0.0f;
    #pragma unroll
    for (int j = 0; j < 8; j++) {
        int jj = g * 8 + j;
        p += s_w[jj] * outputs[(size_t)sel_idx[jj] * Oc + o];
    }
    part[g * 256 + o] = p;
    __syncthreads();
    if (t < 256) {
        out[(size_t)b * Oc + t] = part[t] + part[256 + t] + part[512 + t] + part[768 + t];
    }
}

// ---------------- launch ----------------
extern "C" void kernel_launch(void* const* d_in, const int* in_sizes, int n_in,
                              void* d_out, int out_size) {
    const float* x       = (const float*)d_in[0];
    const float* mean    = (const float*)d_in[1];
    const float* stddev  = (const float*)d_in[2];
    const float* outputs = (const float*)d_in[3];
    float* out = (float*)d_out;

    prep_x_kernel<<<Bc, Dc>>>(x);
    prep_w_kernel<<<Kc, Dc>>>(mean, stddev);
    dim3 grid(Kc / BN, Bc / BM);
    gemm_kernel<<<grid, 256>>>();
    topk_kernel<<<Bc, 1024>>>(outputs, out);
}

// round 3
// speedup vs baseline: 2.5621x; 2.5621x over previous
#include <cuda_runtime.h>
#include <cuda_bf16.h>
#include <cuda_fp16.h>
#include <math.h>
#include <stdint.h>

#define Kc 65536
#define Dc 256
#define Oc 256
#define Bc 1024
#define TOPK 32
#define NCAND 48
#define TWOD 512
#define SHIFT 491.25f
#define HALF_D_LOG2PI 235.2482645f   // 0.5 * 256 * ln(2*pi)

// ---------------- device scratch ----------------
__device__ __nv_bfloat16 g_xb[(size_t)Bc * TWOD];        // 1 MB  [x | -0.5x^2]
__device__ __nv_bfloat16 g_wb[(size_t)Kc * TWOD];        // 64 MB [m*iv | iv]
__device__ float         g_bias[Kc];
__device__ __half        g_lh[(size_t)Bc * Kc];          // 128 MB shifted logits

__device__ __forceinline__ float neg_inf() { return __int_as_float(0xff800000); }

__device__ __forceinline__ uint32_t smem_u32(const void* p) {
    uint32_t a;
    asm("{ .reg .u64 t; cvta.to.shared.u64 t, %1; cvt.u32.u64 %0, t; }" : "=r"(a) : "l"(p));
    return a;
}
__device__ __forceinline__ void cp_async16(uint32_t dst, const void* src) {
    asm volatile("cp.async.cg.shared.global [%0], [%1], 16;" :: "r"(dst), "l"(src));
}
#define CP_COMMIT() asm volatile("cp.async.commit_group;" ::: "memory")
#define CP_WAIT(n)  asm volatile("cp.async.wait_group %0;" :: "n"(n) : "memory")

#define LDSM_X4(r, addr) \
    asm volatile("ldmatrix.sync.aligned.m8n8.x4.shared.b16 {%0,%1,%2,%3}, [%4];" \
        : "=r"((r)[0]), "=r"((r)[1]), "=r"((r)[2]), "=r"((r)[3]) : "r"(addr))

__device__ __forceinline__ void mma16816(float* c, const uint32_t* a, uint32_t b0, uint32_t b1) {
    asm volatile("mma.sync.aligned.m16n8k16.row.col.f32.bf16.bf16.f32 "
        "{%0,%1,%2,%3}, {%4,%5,%6,%7}, {%8,%9}, {%0,%1,%2,%3};"
        : "+f"(c[0]), "+f"(c[1]), "+f"(c[2]), "+f"(c[3])
        : "r"(a[0]), "r"(a[1]), "r"(a[2]), "r"(a[3]), "r"(b0), "r"(b1));
}

// ---------------- prep kernels ----------------
__global__ void prep_x_kernel(const float* __restrict__ x) {
    int b = blockIdx.x, d = threadIdx.x;
    float v = x[b * Dc + d];
    g_xb[(size_t)b * TWOD + d]      = __float2bfloat16(v);
    g_xb[(size_t)b * TWOD + Dc + d] = __float2bfloat16(-0.5f * v * v);
}

__global__ void prep_w_kernel(const float* __restrict__ mean,
                              const float* __restrict__ stddev) {
    int k = blockIdx.x, d = threadIdx.x;
    float s  = stddev[(size_t)k * Dc + d];
    float m  = mean[(size_t)k * Dc + d];
    float iv = 1.0f / (s * s);
    g_wb[(size_t)k * TWOD + d]      = __float2bfloat16(m * iv);
    g_wb[(size_t)k * TWOD + Dc + d] = __float2bfloat16(iv);
    float part = -0.5f * m * m * iv - logf(s);
    #pragma unroll
    for (int off = 16; off > 0; off >>= 1)
        part += __shfl_xor_sync(0xffffffffu, part, off);
    __shared__ float red[8];
    if ((d & 31) == 0) red[d >> 5] = part;
    __syncthreads();
    if (d == 0) {
        float t = 0;
        #pragma unroll
        for (int i = 0; i < 8; i++) t += red[i];
        g_bias[k] = t - HALF_D_LOG2PI;
    }
}

// ---------------- mma.sync bf16 GEMM ----------------
// CTA tile 128(M) x 128(N), BK=32, 3-stage cp.async pipeline.
// 8 warps: 2(M) x 4(N); warp tile 64 x 32.
// smem rows padded to 80B: conflict-free ldmatrix (80r mod 128 distinct phases).
#define NSTAGE 3
#define ROWB   80
#define STAGE_BYTES (128 * ROWB * 2)   // A + B per stage = 20480
#define GEMM_SMEM (NSTAGE * STAGE_BYTES)

__device__ __forceinline__ void load_stage(uint32_t sbase, int st, int m0, int n0, int k0, int tid) {
    uint32_t ab = sbase + st * STAGE_BYTES;
    uint32_t bb = ab + 128 * ROWB;
    #pragma unroll
    for (int i = 0; i < 2; i++) {
        int lin = tid + (i << 8);
        int row = lin >> 2, ch = lin & 3;
        cp_async16(ab + row * ROWB + ch * 16, g_xb + (size_t)(m0 + row) * TWOD + k0 + ch * 8);
        cp_async16(bb + row * ROWB + ch * 16, g_wb + (size_t)(n0 + row) * TWOD + k0 + ch * 8);
    }
    CP_COMMIT();
}

__global__ void __launch_bounds__(256, 2) gemm_kernel() {
    extern __shared__ char smem[];
    uint32_t sbase = smem_u32(smem);
    int tid = threadIdx.x, wid = tid >> 5, lane = tid & 31;
    int m0 = blockIdx.y * 128;
    int n0 = blockIdx.x * 128;
    int wm = wid >> 2;          // 0..1
    int wn = wid & 3;           // 0..3

    float acc[4][4][4];
    #pragma unroll
    for (int mt = 0; mt < 4; mt++)
        #pragma unroll
        for (int nt = 0; nt < 4; nt++)
            #pragma unroll
            for (int q = 0; q < 4; q++) acc[mt][nt][q] = 0.0f;

    load_stage(sbase, 0, m0, n0, 0, tid);
    load_stage(sbase, 1, m0, n0, 32, tid);

    // precompute lane-dependent ldmatrix offsets
    uint32_t a_row = (uint32_t)(wm * 64 + (lane & 15));
    uint32_t a_off = a_row * ROWB + ((lane >> 4) << 4);
    uint32_t b_row = (uint32_t)(wn * 32 + (lane & 7) + ((lane >> 4) << 3));
    uint32_t b_off = b_row * ROWB + (((lane >> 3) & 1) << 4);

    #pragma unroll 1
    for (int it = 0; it < 16; it++) {
        CP_WAIT(1);
        __syncthreads();
        if (it + 2 < 16) load_stage(sbase, (it + 2) % NSTAGE, m0, n0, (it + 2) * 32, tid);

        int st = it % NSTAGE;
        uint32_t ab = sbase + st * STAGE_BYTES;
        uint32_t bb = ab + 128 * ROWB;

        #pragma unroll
        for (int ks = 0; ks < 2; ks++) {
            uint32_t afr[4][4];
            #pragma unroll
            for (int mt = 0; mt < 4; mt++)
                LDSM_X4(afr[mt], ab + a_off + mt * (16 * ROWB) + ks * 32);
            uint32_t bfr[2][4];
            #pragma unroll
            for (int np = 0; np < 2; np++)
                LDSM_X4(bfr[np], bb + b_off + np * (16 * ROWB) + ks * 32);
            #pragma unroll
            for (int mt = 0; mt < 4; mt++)
                #pragma unroll
                for (int nt = 0; nt < 4; nt++)
                    mma16816(acc[mt][nt], afr[mt],
                             bfr[nt >> 1][(nt & 1) * 2], bfr[nt >> 1][(nt & 1) * 2 + 1]);
        }
    }

    // epilogue: add bias + SHIFT, convert to half, store
    #pragma unroll
    for (int nt = 0; nt < 4; nt++) {
        int col = n0 + wn * 32 + nt * 8 + (lane & 3) * 2;
        float2 bb2 = *(const float2*)&g_bias[col];
        float bx = bb2.x + SHIFT, by = bb2.y + SHIFT;
        #pragma unroll
        for (int mt = 0; mt < 4; mt++) {
            int row = m0 + wm * 64 + mt * 16 + (lane >> 2);
            __half2 h0 = __floats2half2_rn(acc[mt][nt][0] + bx, acc[mt][nt][1] + by);
            __half2 h1 = __floats2half2_rn(acc[mt][nt][2] + bx, acc[mt][nt][3] + by);
            *(__half2*)(g_lh + (size_t)row * Kc + col)       = h0;
            *(__half2*)(g_lh + (size_t)(row + 8) * Kc + col) = h1;
        }
    }
}

// ---------------- topk + exact rescore + softmax + gather ----------------
__global__ void __launch_bounds__(1024) topk_kernel(const float* __restrict__ x,
                                                    const float* __restrict__ mean,
                                                    const float* __restrict__ stddev,
                                                    const float* __restrict__ outputs,
                                                    float* __restrict__ out) {
    int b = blockIdx.x, t = threadIdx.x;
    __half* row = g_lh + (size_t)b * Kc;
    const float NI = neg_inf();

    float v[8]; int id[8];
    #pragma unroll
    for (int i = 0; i < 8; i++) { v[i] = NI; id[i] = -1; }

    #pragma unroll
    for (int i = 0; i < 8; i++) {
        int eb = ((i << 10) + t) << 3;     // 8 consecutive halfs
        uint4 pk = *(const uint4*)(row + eb);
        const __half2* hp = (const __half2*)&pk;
        #pragma unroll
        for (int q = 0; q < 4; q++) {
            float2 f = __half22float2(hp[q]);
            float vals[2] = { f.x, f.y };
            #pragma unroll
            for (int z = 0; z < 2; z++) {
                float val = vals[z];
                if (val > v[7]) {
                    v[7] = val; id[7] = eb + q * 2 + z;
                    #pragma unroll
                    for (int p = 7; p > 0; --p)
                        if (v[p] > v[p - 1]) {
                            float tv = v[p]; v[p] = v[p - 1]; v[p - 1] = tv;
                            int ti = id[p]; id[p] = id[p - 1]; id[p - 1] = ti;
                        }
                }
            }
        }
    }

    __shared__ float swv[32];
    __shared__ int   swi[32];
    __shared__ int   s_curi;
    __shared__ int   s_selidx[NCAND];
    __shared__ float s_clp[NCAND];
    __shared__ float s_fv[TOPK];
    __shared__ int   s_fi[TOPK];
    __shared__ float s_w[TOPK];
    __shared__ float part[4 * 256];

    int lane = t & 31, warp = t >> 5;

    for (int r = 0; r < NCAND; r++) {
        float bv = v[0]; int bi = id[0];
        #pragma unroll
        for (int off = 16; off > 0; off >>= 1) {
            float ov = __shfl_down_sync(0xffffffffu, bv, off);
            int   oi = __shfl_down_sync(0xffffffffu, bi, off);
            if (ov > bv) { bv = ov; bi = oi; }
        }
        if (lane == 0) { swv[warp] = bv; swi[warp] = bi; }
        __syncthreads();
        if (warp == 0) {
            bv = swv[lane]; bi = swi[lane];
            #pragma unroll
            for (int off = 16; off > 0; off >>= 1) {
                float ov = __shfl_down_sync(0xffffffffu, bv, off);
                int   oi = __shfl_down_sync(0xffffffffu, bi, off);
                if (ov > bv) { bv = ov; bi = oi; }
            }
            if (lane == 0) { s_curi = bi; s_selidx[r] = bi; }
        }
        __syncthreads();
        int ci = s_curi;
        if (((ci >> 3) & 1023) == t) {
            #pragma unroll
            for (int p = 0; p < 7; p++) { v[p] = v[p + 1]; id[p] = id[p + 1]; }
            v[7] = NI; id[7] = -1;
            row[ci] = __float2half(-60000.0f);
            if (id[0] < 0) {  // exhausted local list: exact rescan (rare)
                #pragma unroll
                for (int i = 0; i < 8; i++) {
                    int eb = ((i << 10) + t) << 3;
                    uint4 pk = *(const uint4*)(row + eb);
                    const __half2* hp = (const __half2*)&pk;
                    #pragma unroll
                    for (int q = 0; q < 4; q++) {
                        float2 f = __half22float2(hp[q]);
                        float vals[2] = { f.x, f.y };
                        #pragma unroll
                        for (int z = 0; z < 2; z++) {
                            float val = vals[z];
                            if (val > v[7]) {
                                v[7] = val; id[7] = eb + q * 2 + z;
                                #pragma unroll
                                for (int p = 7; p > 0; --p)
                                    if (v[p] > v[p - 1]) {
                                        float tv = v[p]; v[p] = v[p - 1]; v[p - 1] = tv;
                                        int ti = id[p]; id[p] = id[p - 1]; id[p - 1] = ti;
                                    }
                            }
                        }
                    }
                }
            }
        }
        __syncthreads();
    }

    // exact fp32 rescore of the 48 candidates (one warp per candidate)
    for (int cc = warp; cc < NCAND; cc += 32) {
        int c = s_selidx[cc];
        float sq = 0.0f, sl = 0.0f;
        #pragma unroll
        for (int jj = 0; jj < 8; jj++) {
            int d = lane + (jj << 5);
            float m  = mean[(size_t)c * Dc + d];
            float sd = stddev[(size_t)c * Dc + d];
            float xv = x[(size_t)b * Dc + d];
            float iv = 1.0f / (sd * sd);
            float df = xv - m;
            sq = fmaf(df * df, iv, sq);
            sl += logf(sd);
        }
        #pragma unroll
        for (int off = 16; off > 0; off >>= 1) {
            sq += __shfl_xor_sync(0xffffffffu, sq, off);
            sl += __shfl_xor_sync(0xffffffffu, sl, off);
        }
        if (lane == 0) s_clp[cc] = -0.5f * sq - sl - HALF_D_LOG2PI;
    }
    __syncthreads();

    // exact top-32 of the 48 rescored values (warp 0)
    if (warp == 0) {
        float va = s_clp[lane]; int ia = lane;
        float vb = (lane < NCAND - 32) ? s_clp[32 + lane] : NI; int ib = 32 + lane;
        for (int r = 0; r < TOPK; r++) {
            float m = (vb > va) ? vb : va;
            int   mi = (vb > va) ? ib : ia;
            float bm = m; int bi = mi;
            #pragma unroll
            for (int off = 16; off > 0; off >>= 1) {
                float ov = __shfl_down_sync(0xffffffffu, bm, off);
                int   oi = __shfl_down_sync(0xffffffffu, bi, off);
                if (ov > bm) { bm = ov; bi = oi; }
            }
            bm = __shfl_sync(0xffffffffu, bm, 0);
            bi = __shfl_sync(0xffffffffu, bi, 0);
            if (lane == 0) { s_fv[r] = bm; s_fi[r] = s_selidx[bi]; }
            if (ia == bi) va = NI;
            if (ib == bi) vb = NI;
        }
    }
    __syncthreads();

    if (t < TOPK) {
        float e = expf(s_fv[t] - s_fv[0]);
        float s = e;
        #pragma unroll
        for (int off = 16; off > 0; off >>= 1)
            s += __shfl_xor_sync(0xffffffffu, s, off);
        s_w[t] = e / s;
    }
    __syncthreads();

    int o = t & 255, g = t >> 8;
    float p = 0.0f;
    #pragma unroll
    for (int j = 0; j < 8; j++) {
        int jj = g * 8 + j;
        p = fmaf(s_w[jj], outputs[(size_t)s_fi[jj] * Oc + o], p);
    }
    part[g * 256 + o] = p;
    __syncthreads();
    if (t < 256)
        out[(size_t)b * Oc + t] = part[t] + part[256 + t] + part[512 + t] + part[768 + t];
}

// ---------------- launch ----------------
extern "C" void kernel_launch(void* const* d_in, const int* in_sizes, int n_in,
                              void* d_out, int out_size) {
    const float* x       = (const float*)d_in[0];
    const float* mean    = (const float*)d_in[1];
    const float* stddev  = (const float*)d_in[2];
    const float* outputs = (const float*)d_in[3];
    float* out = (float*)d_out;

    cudaFuncSetAttribute(gemm_kernel, cudaFuncAttributeMaxDynamicSharedMemorySize, GEMM_SMEM);

    prep_x_kernel<<<Bc, Dc>>>(x);
    prep_w_kernel<<<Kc, Dc>>>(mean, stddev);
    gemm_kernel<<<dim3(Kc / 128, Bc / 128), 256, GEMM_SMEM>>>();
    topk_kernel<<<Bc, 1024>>>(x, mean, stddev, outputs, out);
}

// round 4
// speedup vs baseline: 3.5436x; 1.3831x over previous
#include <cuda_runtime.h>
#include <cuda_bf16.h>
#include <cuda_fp16.h>
#include <math.h>
#include <stdint.h>

#define Kc 65536
#define Dc 256
#define Oc 256
#define Bc 1024
#define TOPK 32
#define NCAND 48
#define NCAP 96
#define TWOD 512
#define SHIFT 491.25f
#define HALF_D_LOG2PI 235.2482645f   // 0.5 * 256 * ln(2*pi)

// ---------------- device scratch ----------------
__device__ __nv_bfloat16 g_xb[(size_t)Bc * TWOD];        // 1 MB  [x | -0.5x^2]
__device__ __nv_bfloat16 g_wb[(size_t)Kc * TWOD];        // 64 MB [m*iv | iv]
__device__ float         g_bias[Kc];
__device__ __half        g_lh[(size_t)Bc * Kc];          // 128 MB shifted logits

__device__ __forceinline__ float neg_inf() { return __int_as_float(0xff800000); }

__device__ __forceinline__ uint32_t smem_u32(const void* p) {
    uint32_t a;
    asm("{ .reg .u64 t; cvta.to.shared.u64 t, %1; cvt.u32.u64 %0, t; }" : "=r"(a) : "l"(p));
    return a;
}
__device__ __forceinline__ void cp_async16(uint32_t dst, const void* src) {
    asm volatile("cp.async.cg.shared.global [%0], [%1], 16;" :: "r"(dst), "l"(src));
}
#define CP_COMMIT() asm volatile("cp.async.commit_group;" ::: "memory")
#define CP_WAIT(n)  asm volatile("cp.async.wait_group %0;" :: "n"(n) : "memory")

#define LDSM_X4(r, addr) \
    asm volatile("ldmatrix.sync.aligned.m8n8.x4.shared.b16 {%0,%1,%2,%3}, [%4];" \
        : "=r"((r)[0]), "=r"((r)[1]), "=r"((r)[2]), "=r"((r)[3]) : "r"(addr))

__device__ __forceinline__ void mma16816(float* c, const uint32_t* a, uint32_t b0, uint32_t b1) {
    asm volatile("mma.sync.aligned.m16n8k16.row.col.f32.bf16.bf16.f32 "
        "{%0,%1,%2,%3}, {%4,%5,%6,%7}, {%8,%9}, {%0,%1,%2,%3};"
        : "+f"(c[0]), "+f"(c[1]), "+f"(c[2]), "+f"(c[3])
        : "r"(a[0]), "r"(a[1]), "r"(a[2]), "r"(a[3]), "r"(b0), "r"(b1));
}

// both halves of a half2 word -> order-preserving 16-bit keys
__device__ __forceinline__ uint32_t key2(uint32_t h2) {
    uint32_t s = h2 & 0x80008000u;
    uint32_t m = 0x80008000u | ((s >> 15) * 0x7FFFu);
    return h2 ^ m;
}

// ---------------- prep kernels ----------------
__global__ void prep_x_kernel(const float* __restrict__ x) {
    int b = blockIdx.x, d = threadIdx.x;
    float v = x[b * Dc + d];
    g_xb[(size_t)b * TWOD + d]      = __float2bfloat16(v);
    g_xb[(size_t)b * TWOD + Dc + d] = __float2bfloat16(-0.5f * v * v);
}

__global__ void prep_w_kernel(const float* __restrict__ mean,
                              const float* __restrict__ stddev) {
    int k = blockIdx.x, d = threadIdx.x;
    float s  = stddev[(size_t)k * Dc + d];
    float m  = mean[(size_t)k * Dc + d];
    float iv = 1.0f / (s * s);
    g_wb[(size_t)k * TWOD + d]      = __float2bfloat16(m * iv);
    g_wb[(size_t)k * TWOD + Dc + d] = __float2bfloat16(iv);
    float part = -0.5f * m * m * iv - logf(s);
    #pragma unroll
    for (int off = 16; off > 0; off >>= 1)
        part += __shfl_xor_sync(0xffffffffu, part, off);
    __shared__ float red[8];
    if ((d & 31) == 0) red[d >> 5] = part;
    __syncthreads();
    if (d == 0) {
        float t = 0;
        #pragma unroll
        for (int i = 0; i < 8; i++) t += red[i];
        g_bias[k] = t - HALF_D_LOG2PI;
    }
}

// ---------------- mma.sync bf16 GEMM ----------------
#define NSTAGE 4
#define ROWB   80
#define STAGE_BYTES (128 * ROWB * 2)   // A + B per stage = 20480
#define GEMM_SMEM (NSTAGE * STAGE_BYTES)

__device__ __forceinline__ void load_stage(uint32_t sbase, int st, int m0, int n0, int k0, int tid) {
    uint32_t ab = sbase + st * STAGE_BYTES;
    uint32_t bb = ab + 128 * ROWB;
    #pragma unroll
    for (int i = 0; i < 2; i++) {
        int lin = tid + (i << 8);
        int row = lin >> 2, ch = lin & 3;
        cp_async16(ab + row * ROWB + ch * 16, g_xb + (size_t)(m0 + row) * TWOD + k0 + ch * 8);
        cp_async16(bb + row * ROWB + ch * 16, g_wb + (size_t)(n0 + row) * TWOD + k0 + ch * 8);
    }
    CP_COMMIT();
}

__global__ void __launch_bounds__(256, 2) gemm_kernel() {
    extern __shared__ char smem[];
    uint32_t sbase = smem_u32(smem);
    int tid = threadIdx.x, wid = tid >> 5, lane = tid & 31;
    int m0 = blockIdx.y * 128;
    int n0 = blockIdx.x * 128;
    int wm = wid >> 2;          // 0..1
    int wn = wid & 3;           // 0..3

    float acc[4][4][4];
    #pragma unroll
    for (int mt = 0; mt < 4; mt++)
        #pragma unroll
        for (int nt = 0; nt < 4; nt++)
            #pragma unroll
            for (int q = 0; q < 4; q++) acc[mt][nt][q] = 0.0f;

    load_stage(sbase, 0, m0, n0, 0, tid);
    load_stage(sbase, 1, m0, n0, 32, tid);
    load_stage(sbase, 2, m0, n0, 64, tid);

    uint32_t a_row = (uint32_t)(wm * 64 + (lane & 15));
    uint32_t a_off = a_row * ROWB + ((lane >> 4) << 4);
    uint32_t b_row = (uint32_t)(wn * 32 + (lane & 7) + ((lane >> 4) << 3));
    uint32_t b_off = b_row * ROWB + (((lane >> 3) & 1) << 4);

    #pragma unroll 1
    for (int it = 0; it < 16; it++) {
        CP_WAIT(2);
        __syncthreads();
        if (it + 3 < 16) load_stage(sbase, (it + 3) % NSTAGE, m0, n0, (it + 3) * 32, tid);

        int st = it % NSTAGE;
        uint32_t ab = sbase + st * STAGE_BYTES;
        uint32_t bb = ab + 128 * ROWB;

        #pragma unroll
        for (int ks = 0; ks < 2; ks++) {
            uint32_t afr[4][4];
            #pragma unroll
            for (int mt = 0; mt < 4; mt++)
                LDSM_X4(afr[mt], ab + a_off + mt * (16 * ROWB) + ks * 32);
            uint32_t bfr[2][4];
            #pragma unroll
            for (int np = 0; np < 2; np++)
                LDSM_X4(bfr[np], bb + b_off + np * (16 * ROWB) + ks * 32);
            #pragma unroll
            for (int mt = 0; mt < 4; mt++)
                #pragma unroll
                for (int nt = 0; nt < 4; nt++)
                    mma16816(acc[mt][nt], afr[mt],
                             bfr[nt >> 1][(nt & 1) * 2], bfr[nt >> 1][(nt & 1) * 2 + 1]);
        }
    }

    #pragma unroll
    for (int nt = 0; nt < 4; nt++) {
        int col = n0 + wn * 32 + nt * 8 + (lane & 3) * 2;
        float2 bb2 = *(const float2*)&g_bias[col];
        float bx = bb2.x + SHIFT, by = bb2.y + SHIFT;
        #pragma unroll
        for (int mt = 0; mt < 4; mt++) {
            int row = m0 + wm * 64 + mt * 16 + (lane >> 2);
            __half2 h0 = __floats2half2_rn(acc[mt][nt][0] + bx, acc[mt][nt][1] + by);
            __half2 h1 = __floats2half2_rn(acc[mt][nt][2] + bx, acc[mt][nt][3] + by);
            *(__half2*)(g_lh + (size_t)row * Kc + col)       = h0;
            *(__half2*)(g_lh + (size_t)(row + 8) * Kc + col) = h1;
        }
    }
}

// ---------------- topk: register-resident radix select + exact rescore ----------------
__global__ void __launch_bounds__(512, 1) topk_kernel(const float* __restrict__ x,
                                                      const float* __restrict__ mean,
                                                      const float* __restrict__ stddev,
                                                      const float* __restrict__ outputs,
                                                      float* __restrict__ out) {
    int b = blockIdx.x, t = threadIdx.x;
    int lane = t & 31, warp = t >> 5;
    const __half* row = g_lh + (size_t)b * Kc;
    const float NI = neg_inf();

    __shared__ uint32_t whist[16 * 256];   // per-warp histograms (16 KB)
    __shared__ uint32_t sS[256];           // suffix sums
    __shared__ int s_hb, s_c1, s_lo, s_cnt;
    __shared__ uint32_t s_cand[NCAP];
    __shared__ float s_clp[NCAP];
    __shared__ float s_fv[TOPK];
    __shared__ int   s_fi[TOPK];
    __shared__ float s_w[TOPK];
    __shared__ float part[2 * 256];

    // load full row into registers: 64 u32 words = 128 halfs/thread
    uint32_t u[64];
    #pragma unroll
    for (int i = 0; i < 16; i++) {
        uint4 pk = *(const uint4*)(row + (((i << 9) + t) << 3));
        u[i * 4 + 0] = pk.x; u[i * 4 + 1] = pk.y;
        u[i * 4 + 2] = pk.z; u[i * 4 + 3] = pk.w;
    }

    uint32_t* wh = &whist[warp * 256];

    // ---- pass 1: high-byte histogram ----
    for (int i = t; i < 16 * 256; i += 512) whist[i] = 0;
    __syncthreads();
    #pragma unroll
    for (int j = 0; j < 64; j++) {
        uint32_t k2 = key2(u[j]);
        atomicAdd(&wh[(k2 >> 8) & 0xFF], 1u);
        atomicAdd(&wh[k2 >> 24], 1u);
    }
    __syncthreads();
    if (t < 256) {
        uint32_t s = 0;
        #pragma unroll
        for (int w = 0; w < 16; w++) s += whist[w * 256 + t];
        sS[t] = s;
    }
    __syncthreads();
    #pragma unroll
    for (int off = 1; off < 256; off <<= 1) {
        uint32_t v = 0;
        if (t < 256 && t + off < 256) v = sS[t + off];
        __syncthreads();
        if (t < 256) sS[t] += v;
        __syncthreads();
    }
    if (t < 256) {
        uint32_t Sb = sS[t];
        uint32_t Sn = (t < 255) ? sS[t + 1] : 0u;
        if (Sb >= NCAND && Sn < NCAND) { s_hb = t; s_c1 = (int)Sn; }
    }
    __syncthreads();
    uint32_t hb = (uint32_t)s_hb;
    int need = NCAND - s_c1;

    // ---- pass 2a: low-byte histogram of boundary bin ----
    for (int i = t; i < 16 * 256; i += 512) whist[i] = 0;
    __syncthreads();
    #pragma unroll
    for (int j = 0; j < 64; j++) {
        uint32_t k2 = key2(u[j]);
        uint32_t klo = k2 & 0xFFFFu, khi = k2 >> 16;
        if ((klo >> 8) == hb) atomicAdd(&wh[klo & 0xFF], 1u);
        if ((khi >> 8) == hb) atomicAdd(&wh[khi & 0xFF], 1u);
    }
    __syncthreads();
    if (t < 256) {
        uint32_t s = 0;
        #pragma unroll
        for (int w = 0; w < 16; w++) s += whist[w * 256 + t];
        sS[t] = s;
    }
    __syncthreads();
    #pragma unroll
    for (int off = 1; off < 256; off <<= 1) {
        uint32_t v = 0;
        if (t < 256 && t + off < 256) v = sS[t + off];
        __syncthreads();
        if (t < 256) sS[t] += v;
        __syncthreads();
    }
    if (t < 256) {
        uint32_t Sb = sS[t];
        uint32_t Sn = (t < 255) ? sS[t + 1] : 0u;
        if ((int)Sb >= need && (int)Sn < need) s_lo = t;
    }
    if (t == 0) s_cnt = 0;
    __syncthreads();
    uint32_t T = (hb << 8) | (uint32_t)s_lo;

    // ---- pass 2b: collect candidates with key >= T ----
    #pragma unroll
    for (int j = 0; j < 64; j++) {
        uint32_t k2 = key2(u[j]);
        uint32_t idx0 = ((((uint32_t)(j >> 2) << 9) + t) << 3) + (((uint32_t)j & 3) << 1);
        uint32_t klo = k2 & 0xFFFFu, khi = k2 >> 16;
        if (klo >= T) {
            int p = atomicAdd(&s_cnt, 1);
            if (p < NCAP) s_cand[p] = (klo << 16) | idx0;
        }
        if (khi >= T) {
            int p = atomicAdd(&s_cnt, 1);
            if (p < NCAP) s_cand[p] = (khi << 16) | (idx0 + 1);
        }
    }
    if (t < NCAP) s_clp[t] = NI;
    __syncthreads();
    int M = s_cnt < NCAP ? s_cnt : NCAP;

    // ---- exact fp32 rescore (one warp per candidate) ----
    for (int cc = warp; cc < M; cc += 16) {
        int c = (int)(s_cand[cc] & 0xFFFFu);
        float sq = 0.0f, sl = 0.0f;
        #pragma unroll
        for (int jj = 0; jj < 8; jj++) {
            int d = lane + (jj << 5);
            float m  = mean[(size_t)c * Dc + d];
            float sd = stddev[(size_t)c * Dc + d];
            float xv = x[(size_t)b * Dc + d];
            float iv = 1.0f / (sd * sd);
            float df = xv - m;
            sq = fmaf(df * df, iv, sq);
            sl += logf(sd);
        }
        #pragma unroll
        for (int off = 16; off > 0; off >>= 1) {
            sq += __shfl_xor_sync(0xffffffffu, sq, off);
            sl += __shfl_xor_sync(0xffffffffu, sl, off);
        }
        if (lane == 0) s_clp[cc] = -0.5f * sq - sl - HALF_D_LOG2PI;
    }
    __syncthreads();

    // ---- exact top-32 of up to 96 rescored values (warp 0, 3 slots/lane) ----
    if (warp == 0) {
        float va[3]; int ia[3];
        #pragma unroll
        for (int q = 0; q < 3; q++) { ia[q] = lane + q * 32; va[q] = s_clp[ia[q]]; }
        for (int r = 0; r < TOPK; r++) {
            float m = va[0]; int mi = ia[0];
            if (va[1] > m) { m = va[1]; mi = ia[1]; }
            if (va[2] > m) { m = va[2]; mi = ia[2]; }
            float bm = m; int bi = mi;
            #pragma unroll
            for (int off = 16; off > 0; off >>= 1) {
                float ov = __shfl_down_sync(0xffffffffu, bm, off);
                int   oi = __shfl_down_sync(0xffffffffu, bi, off);
                if (ov > bm) { bm = ov; bi = oi; }
            }
            bm = __shfl_sync(0xffffffffu, bm, 0);
            bi = __shfl_sync(0xffffffffu, bi, 0);
            if (lane == 0) { s_fv[r] = bm; s_fi[r] = (int)(s_cand[bi] & 0xFFFFu); }
            #pragma unroll
            for (int q = 0; q < 3; q++) if (ia[q] == bi) va[q] = NI;
        }
    }
    __syncthreads();

    if (t < TOPK) {
        float e = expf(s_fv[t] - s_fv[0]);
        float s = e;
        #pragma unroll
        for (int off = 16; off > 0; off >>= 1)
            s += __shfl_xor_sync(0xffffffffu, s, off);
        s_w[t] = e / s;
    }
    __syncthreads();

    int o = t & 255, g = t >> 8;   // g in {0,1}
    float p = 0.0f;
    #pragma unroll
    for (int j = 0; j < 16; j++) {
        int jj = g * 16 + j;
        p = fmaf(s_w[jj], outputs[(size_t)s_fi[jj] * Oc + o], p);
    }
    part[g * 256 + o] = p;
    __syncthreads();
    if (t < 256)
        out[(size_t)b * Oc + t] = part[t] + part[256 + t];
}

// ---------------- launch ----------------
extern "C" void kernel_launch(void* const* d_in, const int* in_sizes, int n_in,
                              void* d_out, int out_size) {
    const float* x       = (const float*)d_in[0];
    const float* mean    = (const float*)d_in[1];
    const float* stddev  = (const float*)d_in[2];
    const float* outputs = (const float*)d_in[3];
    float* out = (float*)d_out;

    cudaFuncSetAttribute(gemm_kernel, cudaFuncAttributeMaxDynamicSharedMemorySize, GEMM_SMEM);

    prep_x_kernel<<<Bc, Dc>>>(x);
    prep_w_kernel<<<Kc, Dc>>>(mean, stddev);
    gemm_kernel<<<dim3(Kc / 128, Bc / 128), 256, GEMM_SMEM>>>();
    topk_kernel<<<Bc, 512>>>(x, mean, stddev, outputs, out);
}

// round 5
// speedup vs baseline: 4.2067x; 1.1871x over previous
#include <cuda_runtime.h>
#include <cuda_bf16.h>
#include <cuda_fp16.h>
#include <math.h>
#include <stdint.h>

#define Kc 65536
#define Dc 256
#define Oc 256
#define Bc 1024
#define TOPK 32
#define NCAND 48
#define NCAP 96
#define NTILES 512
#define TCAP 128
#define TWOD 512
#define SHIFT 491.25f
#define HALF_D_LOG2PI 235.2482645f   // 0.5 * 256 * ln(2*pi)

// ---------------- device scratch ----------------
__device__ __nv_bfloat16 g_xb[(size_t)Bc * TWOD];        // 1 MB  [x | -0.5x^2]
__device__ __nv_bfloat16 g_wb[(size_t)Kc * TWOD];        // 64 MB [m*iv | iv]
__device__ float         g_bias[Kc];
__device__ __half        g_lh[(size_t)Bc * Kc];          // 128 MB shifted logits
__device__ float         g_tmax[(size_t)Bc * NTILES];    // 2 MB per-row per-tile max

__device__ __forceinline__ float neg_inf() { return __int_as_float(0xff800000); }

__device__ __forceinline__ uint32_t smem_u32(const void* p) {
    uint32_t a;
    asm("{ .reg .u64 t; cvta.to.shared.u64 t, %1; cvt.u32.u64 %0, t; }" : "=r"(a) : "l"(p));
    return a;
}
__device__ __forceinline__ void cp_async16(uint32_t dst, const void* src) {
    asm volatile("cp.async.cg.shared.global [%0], [%1], 16;" :: "r"(dst), "l"(src));
}
#define CP_COMMIT() asm volatile("cp.async.commit_group;" ::: "memory")
#define CP_WAIT(n)  asm volatile("cp.async.wait_group %0;" :: "n"(n) : "memory")

#define LDSM_X4(r, addr) \
    asm volatile("ldmatrix.sync.aligned.m8n8.x4.shared.b16 {%0,%1,%2,%3}, [%4];" \
        : "=r"((r)[0]), "=r"((r)[1]), "=r"((r)[2]), "=r"((r)[3]) : "r"(addr))

__device__ __forceinline__ void mma16816(float* c, const uint32_t* a, uint32_t b0, uint32_t b1) {
    asm volatile("mma.sync.aligned.m16n8k16.row.col.f32.bf16.bf16.f32 "
        "{%0,%1,%2,%3}, {%4,%5,%6,%7}, {%8,%9}, {%0,%1,%2,%3};"
        : "+f"(c[0]), "+f"(c[1]), "+f"(c[2]), "+f"(c[3])
        : "r"(a[0]), "r"(a[1]), "r"(a[2]), "r"(a[3]), "r"(b0), "r"(b1));
}

// both halves of a half2 word -> order-preserving 16-bit keys
__device__ __forceinline__ uint32_t key2(uint32_t h2) {
    uint32_t s = h2 & 0x80008000u;
    uint32_t m = 0x80008000u | ((s >> 15) * 0x7FFFu);
    return h2 ^ m;
}
__device__ __forceinline__ uint32_t fkey(float f) {
    uint32_t u = __float_as_uint(f);
    return (u & 0x80000000u) ? ~u : (u | 0x80000000u);
}

// ---------------- prep kernels ----------------
__global__ void prep_x_kernel(const float* __restrict__ x) {
    int b = blockIdx.x, d = threadIdx.x;
    float v = x[b * Dc + d];
    g_xb[(size_t)b * TWOD + d]      = __float2bfloat16(v);
    g_xb[(size_t)b * TWOD + Dc + d] = __float2bfloat16(-0.5f * v * v);
}

__global__ void prep_w_kernel(const float* __restrict__ mean,
                              const float* __restrict__ stddev) {
    int k = blockIdx.x, d = threadIdx.x;
    float s  = stddev[(size_t)k * Dc + d];
    float m  = mean[(size_t)k * Dc + d];
    float iv = 1.0f / (s * s);
    g_wb[(size_t)k * TWOD + d]      = __float2bfloat16(m * iv);
    g_wb[(size_t)k * TWOD + Dc + d] = __float2bfloat16(iv);
    float part = -0.5f * m * m * iv - logf(s);
    #pragma unroll
    for (int off = 16; off > 0; off >>= 1)
        part += __shfl_xor_sync(0xffffffffu, part, off);
    __shared__ float red[8];
    if ((d & 31) == 0) red[d >> 5] = part;
    __syncthreads();
    if (d == 0) {
        float t = 0;
        #pragma unroll
        for (int i = 0; i < 8; i++) t += red[i];
        g_bias[k] = t - HALF_D_LOG2PI;
    }
}

// ---------------- mma.sync bf16 GEMM (+ per-tile row max) ----------------
#define NSTAGE 4
#define ROWB   80
#define STAGE_BYTES (128 * ROWB * 2)   // A + B per stage = 20480
#define GEMM_SMEM (NSTAGE * STAGE_BYTES)

__device__ __forceinline__ void load_stage(uint32_t sbase, int st, int m0, int n0, int k0, int tid) {
    uint32_t ab = sbase + st * STAGE_BYTES;
    uint32_t bb = ab + 128 * ROWB;
    #pragma unroll
    for (int i = 0; i < 2; i++) {
        int lin = tid + (i << 8);
        int row = lin >> 2, ch = lin & 3;
        cp_async16(ab + row * ROWB + ch * 16, g_xb + (size_t)(m0 + row) * TWOD + k0 + ch * 8);
        cp_async16(bb + row * ROWB + ch * 16, g_wb + (size_t)(n0 + row) * TWOD + k0 + ch * 8);
    }
    CP_COMMIT();
}

__global__ void __launch_bounds__(256, 2) gemm_kernel() {
    extern __shared__ char smem[];
    __shared__ float smax[128][4];
    uint32_t sbase = smem_u32(smem);
    int tid = threadIdx.x, wid = tid >> 5, lane = tid & 31;
    int m0 = blockIdx.y * 128;
    int n0 = blockIdx.x * 128;
    int wm = wid >> 2;          // 0..1
    int wn = wid & 3;           // 0..3

    float acc[4][4][4];
    #pragma unroll
    for (int mt = 0; mt < 4; mt++)
        #pragma unroll
        for (int nt = 0; nt < 4; nt++)
            #pragma unroll
            for (int q = 0; q < 4; q++) acc[mt][nt][q] = 0.0f;

    load_stage(sbase, 0, m0, n0, 0, tid);
    load_stage(sbase, 1, m0, n0, 32, tid);
    load_stage(sbase, 2, m0, n0, 64, tid);

    uint32_t a_row = (uint32_t)(wm * 64 + (lane & 15));
    uint32_t a_off = a_row * ROWB + ((lane >> 4) << 4);
    uint32_t b_row = (uint32_t)(wn * 32 + (lane & 7) + ((lane >> 4) << 3));
    uint32_t b_off = b_row * ROWB + (((lane >> 3) & 1) << 4);

    #pragma unroll 1
    for (int it = 0; it < 16; it++) {
        CP_WAIT(2);
        __syncthreads();
        if (it + 3 < 16) load_stage(sbase, (it + 3) % NSTAGE, m0, n0, (it + 3) * 32, tid);

        int st = it % NSTAGE;
        uint32_t ab = sbase + st * STAGE_BYTES;
        uint32_t bb = ab + 128 * ROWB;

        #pragma unroll
        for (int ks = 0; ks < 2; ks++) {
            uint32_t afr[4][4];
            #pragma unroll
            for (int mt = 0; mt < 4; mt++)
                LDSM_X4(afr[mt], ab + a_off + mt * (16 * ROWB) + ks * 32);
            uint32_t bfr[2][4];
            #pragma unroll
            for (int np = 0; np < 2; np++)
                LDSM_X4(bfr[np], bb + b_off + np * (16 * ROWB) + ks * 32);
            #pragma unroll
            for (int mt = 0; mt < 4; mt++)
                #pragma unroll
                for (int nt = 0; nt < 4; nt++)
                    mma16816(acc[mt][nt], afr[mt],
                             bfr[nt >> 1][(nt & 1) * 2], bfr[nt >> 1][(nt & 1) * 2 + 1]);
        }
    }

    const float NI = neg_inf();
    float rmA[4], rmB[4];
    #pragma unroll
    for (int mt = 0; mt < 4; mt++) { rmA[mt] = NI; rmB[mt] = NI; }

    #pragma unroll
    for (int nt = 0; nt < 4; nt++) {
        int col = n0 + wn * 32 + nt * 8 + (lane & 3) * 2;
        float2 bb2 = *(const float2*)&g_bias[col];
        float bx = bb2.x + SHIFT, by = bb2.y + SHIFT;
        #pragma unroll
        for (int mt = 0; mt < 4; mt++) {
            int row = m0 + wm * 64 + mt * 16 + (lane >> 2);
            float a0 = acc[mt][nt][0] + bx, a1 = acc[mt][nt][1] + by;
            float a2 = acc[mt][nt][2] + bx, a3 = acc[mt][nt][3] + by;
            rmA[mt] = fmaxf(rmA[mt], fmaxf(a0, a1));
            rmB[mt] = fmaxf(rmB[mt], fmaxf(a2, a3));
            *(__half2*)(g_lh + (size_t)row * Kc + col)       = __floats2half2_rn(a0, a1);
            *(__half2*)(g_lh + (size_t)(row + 8) * Kc + col) = __floats2half2_rn(a2, a3);
        }
    }

    // reduce row max across the 4 lanes sharing a row, then across warps
    #pragma unroll
    for (int mt = 0; mt < 4; mt++) {
        #pragma unroll
        for (int off = 1; off < 4; off <<= 1) {
            rmA[mt] = fmaxf(rmA[mt], __shfl_xor_sync(0xffffffffu, rmA[mt], off));
            rmB[mt] = fmaxf(rmB[mt], __shfl_xor_sync(0xffffffffu, rmB[mt], off));
        }
        if ((lane & 3) == 0) {
            int lr = wm * 64 + mt * 16 + (lane >> 2);
            smax[lr][wn]     = rmA[mt];
            smax[lr + 8][wn] = rmB[mt];
        }
    }
    __syncthreads();
    if (tid < 128) {
        float m = fmaxf(fmaxf(smax[tid][0], smax[tid][1]), fmaxf(smax[tid][2], smax[tid][3]));
        g_tmax[(size_t)(m0 + tid) * NTILES + blockIdx.x] = m;
    }
}

// ---------------- topk: tile-max guided selection + exact rescore ----------------
__global__ void __launch_bounds__(512) topk_kernel(const float* __restrict__ x,
                                                   const float* __restrict__ mean,
                                                   const float* __restrict__ stddev,
                                                   const float* __restrict__ outputs,
                                                   float* __restrict__ out) {
    int b = blockIdx.x, t = threadIdx.x;
    int lane = t & 31, warp = t >> 5;
    const float NI = neg_inf();

    __shared__ int   s_tiles[TCAP];
    __shared__ int   s_nt, s_cnt;
    __shared__ int   sred[16];
    __shared__ uint32_t s_cand[NCAP];
    __shared__ float s_clp[NCAP];
    __shared__ float s_fv[TOPK];
    __shared__ int   s_fi[TOPK];
    __shared__ float s_w[TOPK];
    __shared__ float part[2 * 256];

    // ---- stage 1: tile-max threshold via block-vote binary search ----
    uint32_t tk = fkey(g_tmax[(size_t)b * NTILES + t]);
    uint32_t cur = 0;
    #pragma unroll 1
    for (int bit = 31; bit >= 0; --bit) {
        uint32_t T = cur | (1u << bit);
        int n = __syncthreads_count(tk >= T);
        if (n >= NCAND) cur = T;
    }
    if (t == 0) s_nt = 0;
    __syncthreads();
    if (tk >= cur) {
        int p = atomicAdd(&s_nt, 1);
        if (p < TCAP) s_tiles[p] = t;
    }
    __syncthreads();
    int ntl = s_nt < TCAP ? s_nt : TCAP;
    int total = ntl * 64;          // u32 words across selected tiles

    // ---- stage 2: gather selected tiles into registers as 16-bit keys ----
    const uint32_t* row32 = (const uint32_t*)(g_lh + (size_t)b * Kc);
    uint32_t u[16];
    #pragma unroll
    for (int i = 0; i < 16; i++) {
        int w = t + (i << 9);
        if (w < total) {
            int tile = s_tiles[w >> 6];
            u[i] = key2(row32[tile * 64 + (w & 63)]);
        } else {
            u[i] = 0x03FF03FFu;    // key of -inf in both halves
        }
    }

    // ---- stage 3: exact 16-bit threshold via block-sum binary search ----
    uint32_t cur16 = 0;
    #pragma unroll 1
    for (int bit = 15; bit >= 0; --bit) {
        uint32_t T = cur16 | (1u << bit);
        int c = 0;
        #pragma unroll
        for (int i = 0; i < 16; i++)
            c += ((u[i] & 0xFFFFu) >= T) + ((u[i] >> 16) >= T);
        #pragma unroll
        for (int off = 16; off > 0; off >>= 1)
            c += __shfl_xor_sync(0xffffffffu, c, off);
        __syncthreads();
        if (lane == 0) sred[warp] = c;
        __syncthreads();
        int n = 0;
        #pragma unroll
        for (int w = 0; w < 16; w++) n += sred[w];
        if (n >= NCAND) cur16 = T;
    }
    if (t == 0) s_cnt = 0;
    if (t < NCAP) s_clp[t] = NI;
    __syncthreads();

    // ---- stage 4: collect candidates ----
    #pragma unroll
    for (int i = 0; i < 16; i++) {
        int w = t + (i << 9);
        if (w < total) {
            uint32_t klo = u[i] & 0xFFFFu, khi = u[i] >> 16;
            uint32_t idx = (uint32_t)(s_tiles[w >> 6] * 128 + (w & 63) * 2);
            if (klo >= cur16) {
                int p = atomicAdd(&s_cnt, 1);
                if (p < NCAP) s_cand[p] = (klo << 16) | idx;
            }
            if (khi >= cur16) {
                int p = atomicAdd(&s_cnt, 1);
                if (p < NCAP) s_cand[p] = (khi << 16) | (idx + 1);
            }
        }
    }
    __syncthreads();
    int M = s_cnt < NCAP ? s_cnt : NCAP;

    // ---- exact fp32 rescore (one warp per candidate) ----
    for (int cc = warp; cc < M; cc += 16) {
        int c = (int)(s_cand[cc] & 0xFFFFu);
        float sq = 0.0f, sl = 0.0f;
        #pragma unroll
        for (int jj = 0; jj < 8; jj++) {
            int d = lane + (jj << 5);
            float m  = mean[(size_t)c * Dc + d];
            float sd = stddev[(size_t)c * Dc + d];
            float xv = x[(size_t)b * Dc + d];
            float iv = 1.0f / (sd * sd);
            float df = xv - m;
            sq = fmaf(df * df, iv, sq);
            sl += logf(sd);
        }
        #pragma unroll
        for (int off = 16; off > 0; off >>= 1) {
            sq += __shfl_xor_sync(0xffffffffu, sq, off);
            sl += __shfl_xor_sync(0xffffffffu, sl, off);
        }
        if (lane == 0) s_clp[cc] = -0.5f * sq - sl - HALF_D_LOG2PI;
    }
    __syncthreads();

    // ---- exact top-32 of up to 96 rescored values (warp 0, 3 slots/lane) ----
    if (warp == 0) {
        float va[3]; int ia[3];
        #pragma unroll
        for (int q = 0; q < 3; q++) { ia[q] = lane + q * 32; va[q] = s_clp[ia[q]]; }
        for (int r = 0; r < TOPK; r++) {
            float m = va[0]; int mi = ia[0];
            if (va[1] > m) { m = va[1]; mi = ia[1]; }
            if (va[2] > m) { m = va[2]; mi = ia[2]; }
            float bm = m; int bi = mi;
            #pragma unroll
            for (int off = 16; off > 0; off >>= 1) {
                float ov = __shfl_down_sync(0xffffffffu, bm, off);
                int   oi = __shfl_down_sync(0xffffffffu, bi, off);
                if (ov > bm) { bm = ov; bi = oi; }
            }
            bm = __shfl_sync(0xffffffffu, bm, 0);
            bi = __shfl_sync(0xffffffffu, bi, 0);
            if (lane == 0) { s_fv[r] = bm; s_fi[r] = (int)(s_cand[bi] & 0xFFFFu); }
            #pragma unroll
            for (int q = 0; q < 3; q++) if (ia[q] == bi) va[q] = NI;
        }
    }
    __syncthreads();

    if (t < TOPK) {
        float e = expf(s_fv[t] - s_fv[0]);
        float s = e;
        #pragma unroll
        for (int off = 16; off > 0; off >>= 1)
            s += __shfl_xor_sync(0xffffffffu, s, off);
        s_w[t] = e / s;
    }
    __syncthreads();

    int o = t & 255, g = t >> 8;   // g in {0,1}
    float p = 0.0f;
    #pragma unroll
    for (int j = 0; j < 16; j++) {
        int jj = g * 16 + j;
        p = fmaf(s_w[jj], outputs[(size_t)s_fi[jj] * Oc + o], p);
    }
    part[g * 256 + o] = p;
    __syncthreads();
    if (t < 256)
        out[(size_t)b * Oc + t] = part[t] + part[256 + t];
}

// ---------------- launch ----------------
extern "C" void kernel_launch(void* const* d_in, const int* in_sizes, int n_in,
                              void* d_out, int out_size) {
    const float* x       = (const float*)d_in[0];
    const float* mean    = (const float*)d_in[1];
    const float* stddev  = (const float*)d_in[2];
    const float* outputs = (const float*)d_in[3];
    float* out = (float*)d_out;

    cudaFuncSetAttribute(gemm_kernel, cudaFuncAttributeMaxDynamicSharedMemorySize, GEMM_SMEM);

    prep_x_kernel<<<Bc, Dc>>>(x);
    prep_w_kernel<<<Kc, Dc>>>(mean, stddev);
    gemm_kernel<<<dim3(Kc / 128, Bc / 128), 256, GEMM_SMEM>>>();
    topk_kernel<<<Bc, 512>>>(x, mean, stddev, outputs, out);
}

// round 6
// speedup vs baseline: 6.2002x; 1.4739x over previous
#include <cuda_runtime.h>
#include <cuda_bf16.h>
#include <cuda_fp16.h>
#include <math.h>
#include <stdint.h>

#define Kc 65536
#define Dc 256
#define Oc 256
#define Bc 1024
#define TOPK 32
#define NCAND 48
#define NCAP 96
#define NTILES 512
#define TCAP 128
#define TWOD 512
#define SHIFT_FULL 491.25f
#define SHIFT_UNI  363.25f
#define HALF_D_LOG2PI 235.2482645f   // 0.5 * 256 * ln(2*pi)

// ---------------- device scratch ----------------
__device__ __nv_bfloat16 g_xb[(size_t)Bc * TWOD];        // 1 MB  [x | -0.5x^2]
__device__ __nv_bfloat16 g_wb[(size_t)Kc * TWOD];        // 64 MB [m*iv | iv]
__device__ float         g_bias[Kc];
__device__ __half        g_lh[(size_t)Bc * Kc];          // 128 MB shifted logits
__device__ float         g_tmax[(size_t)Bc * NTILES];    // 2 MB per-row per-tile max
__device__ int           g_flag;                          // 1 => stddev == 1 everywhere

__device__ __forceinline__ float neg_inf() { return __int_as_float(0xff800000); }

__device__ __forceinline__ uint32_t smem_u32(const void* p) {
    uint32_t a;
    asm("{ .reg .u64 t; cvta.to.shared.u64 t, %1; cvt.u32.u64 %0, t; }" : "=r"(a) : "l"(p));
    return a;
}
__device__ __forceinline__ void cp_async16(uint32_t dst, const void* src) {
    asm volatile("cp.async.cg.shared.global [%0], [%1], 16;" :: "r"(dst), "l"(src));
}
#define CP_COMMIT() asm volatile("cp.async.commit_group;" ::: "memory")
#define CP_WAIT(n)  asm volatile("cp.async.wait_group %0;" :: "n"(n) : "memory")

#define LDSM_X4(r, addr) \
    asm volatile("ldmatrix.sync.aligned.m8n8.x4.shared.b16 {%0,%1,%2,%3}, [%4];" \
        : "=r"((r)[0]), "=r"((r)[1]), "=r"((r)[2]), "=r"((r)[3]) : "r"(addr))

__device__ __forceinline__ void mma16816(float* c, const uint32_t* a, uint32_t b0, uint32_t b1) {
    asm volatile("mma.sync.aligned.m16n8k16.row.col.f32.bf16.bf16.f32 "
        "{%0,%1,%2,%3}, {%4,%5,%6,%7}, {%8,%9}, {%0,%1,%2,%3};"
        : "+f"(c[0]), "+f"(c[1]), "+f"(c[2]), "+f"(c[3])
        : "r"(a[0]), "r"(a[1]), "r"(a[2]), "r"(a[3]), "r"(b0), "r"(b1));
}

// both halves of a half2 word -> order-preserving 16-bit keys
__device__ __forceinline__ uint32_t key2(uint32_t h2) {
    uint32_t s = h2 & 0x80008000u;
    uint32_t m = 0x80008000u | ((s >> 15) * 0x7FFFu);
    return h2 ^ m;
}
__device__ __forceinline__ uint32_t fkey(float f) {
    uint32_t u = __float_as_uint(f);
    return (u & 0x80000000u) ? ~u : (u | 0x80000000u);
}

// ---------------- prep kernels ----------------
__global__ void prep_x_kernel(const float* __restrict__ x) {
    int b = blockIdx.x, d = threadIdx.x;
    float v = x[b * Dc + d];
    g_xb[(size_t)b * TWOD + d]      = __float2bfloat16(v);
    g_xb[(size_t)b * TWOD + Dc + d] = __float2bfloat16(-0.5f * v * v);
    if (b == 0 && d == 0) g_flag = 1;   // reset each launch (graph-replay safe)
}

__global__ void prep_w_kernel(const float* __restrict__ mean,
                              const float* __restrict__ stddev) {
    int k = blockIdx.x, d = threadIdx.x;
    float s  = stddev[(size_t)k * Dc + d];
    float m  = mean[(size_t)k * Dc + d];
    float iv = 1.0f / (s * s);
    g_wb[(size_t)k * TWOD + d]      = __float2bfloat16(m * iv);
    g_wb[(size_t)k * TWOD + Dc + d] = __float2bfloat16(iv);
    if (s != 1.0f) g_flag = 0;
    float part = -0.5f * m * m * iv - logf(s);
    #pragma unroll
    for (int off = 16; off > 0; off >>= 1)
        part += __shfl_xor_sync(0xffffffffu, part, off);
    __shared__ float red[8];
    if ((d & 31) == 0) red[d >> 5] = part;
    __syncthreads();
    if (d == 0) {
        float t = 0;
        #pragma unroll
        for (int i = 0; i < 8; i++) t += red[i];
        g_bias[k] = t - HALF_D_LOG2PI;
    }
}

// ---------------- mma.sync bf16 GEMM (+ per-tile row max) ----------------
#define NSTAGE 4
#define ROWB   80
#define STAGE_BYTES (128 * ROWB * 2)   // A + B per stage = 20480
#define GEMM_SMEM (NSTAGE * STAGE_BYTES)

__device__ __forceinline__ void load_stage(uint32_t sbase, int st, int m0, int n0, int k0, int tid) {
    uint32_t ab = sbase + st * STAGE_BYTES;
    uint32_t bb = ab + 128 * ROWB;
    #pragma unroll
    for (int i = 0; i < 2; i++) {
        int lin = tid + (i << 8);
        int row = lin >> 2, ch = lin & 3;
        cp_async16(ab + row * ROWB + ch * 16, g_xb + (size_t)(m0 + row) * TWOD + k0 + ch * 8);
        cp_async16(bb + row * ROWB + ch * 16, g_wb + (size_t)(n0 + row) * TWOD + k0 + ch * 8);
    }
    CP_COMMIT();
}

__global__ void __launch_bounds__(256, 2) gemm_kernel() {
    extern __shared__ char smem[];
    __shared__ float smax[128][4];
    uint32_t sbase = smem_u32(smem);
    int tid = threadIdx.x, wid = tid >> 5, lane = tid & 31;
    int m0 = blockIdx.y * 128;
    int n0 = blockIdx.x * 128;
    int wm = wid >> 2;          // 0..1
    int wn = wid & 3;           // 0..3

    int uni = g_flag;
    int KT = uni ? 8 : 16;      // number of 32-wide k tiles
    float SHIFTV = uni ? SHIFT_UNI : SHIFT_FULL;

    float acc[4][4][4];
    #pragma unroll
    for (int mt = 0; mt < 4; mt++)
        #pragma unroll
        for (int nt = 0; nt < 4; nt++)
            #pragma unroll
            for (int q = 0; q < 4; q++) acc[mt][nt][q] = 0.0f;

    load_stage(sbase, 0, m0, n0, 0, tid);
    load_stage(sbase, 1, m0, n0, 32, tid);
    load_stage(sbase, 2, m0, n0, 64, tid);

    uint32_t a_row = (uint32_t)(wm * 64 + (lane & 15));
    uint32_t a_off = a_row * ROWB + ((lane >> 4) << 4);
    uint32_t b_row = (uint32_t)(wn * 32 + (lane & 7) + ((lane >> 4) << 3));
    uint32_t b_off = b_row * ROWB + (((lane >> 3) & 1) << 4);

    #pragma unroll 1
    for (int it = 0; it < KT; it++) {
        CP_WAIT(2);
        __syncthreads();
        if (it + 3 < KT) load_stage(sbase, (it + 3) % NSTAGE, m0, n0, (it + 3) * 32, tid);

        int st = it % NSTAGE;
        uint32_t ab = sbase + st * STAGE_BYTES;
        uint32_t bb = ab + 128 * ROWB;

        #pragma unroll
        for (int ks = 0; ks < 2; ks++) {
            uint32_t afr[4][4];
            #pragma unroll
            for (int mt = 0; mt < 4; mt++)
                LDSM_X4(afr[mt], ab + a_off + mt * (16 * ROWB) + ks * 32);
            uint32_t bfr[2][4];
            #pragma unroll
            for (int np = 0; np < 2; np++)
                LDSM_X4(bfr[np], bb + b_off + np * (16 * ROWB) + ks * 32);
            #pragma unroll
            for (int mt = 0; mt < 4; mt++)
                #pragma unroll
                for (int nt = 0; nt < 4; nt++)
                    mma16816(acc[mt][nt], afr[mt],
                             bfr[nt >> 1][(nt & 1) * 2], bfr[nt >> 1][(nt & 1) * 2 + 1]);
        }
    }
    CP_WAIT(0);

    const float NI = neg_inf();
    float rmA[4], rmB[4];
    #pragma unroll
    for (int mt = 0; mt < 4; mt++) { rmA[mt] = NI; rmB[mt] = NI; }

    #pragma unroll
    for (int nt = 0; nt < 4; nt++) {
        int col = n0 + wn * 32 + nt * 8 + (lane & 3) * 2;
        float2 bb2 = *(const float2*)&g_bias[col];
        float bx = bb2.x + SHIFTV, by = bb2.y + SHIFTV;
        #pragma unroll
        for (int mt = 0; mt < 4; mt++) {
            int row = m0 + wm * 64 + mt * 16 + (lane >> 2);
            float a0 = acc[mt][nt][0] + bx, a1 = acc[mt][nt][1] + by;
            float a2 = acc[mt][nt][2] + bx, a3 = acc[mt][nt][3] + by;
            rmA[mt] = fmaxf(rmA[mt], fmaxf(a0, a1));
            rmB[mt] = fmaxf(rmB[mt], fmaxf(a2, a3));
            *(__half2*)(g_lh + (size_t)row * Kc + col)       = __floats2half2_rn(a0, a1);
            *(__half2*)(g_lh + (size_t)(row + 8) * Kc + col) = __floats2half2_rn(a2, a3);
        }
    }

    #pragma unroll
    for (int mt = 0; mt < 4; mt++) {
        #pragma unroll
        for (int off = 1; off < 4; off <<= 1) {
            rmA[mt] = fmaxf(rmA[mt], __shfl_xor_sync(0xffffffffu, rmA[mt], off));
            rmB[mt] = fmaxf(rmB[mt], __shfl_xor_sync(0xffffffffu, rmB[mt], off));
        }
        if ((lane & 3) == 0) {
            int lr = wm * 64 + mt * 16 + (lane >> 2);
            smax[lr][wn]     = rmA[mt];
            smax[lr + 8][wn] = rmB[mt];
        }
    }
    __syncthreads();
    if (tid < 128) {
        float m = fmaxf(fmaxf(smax[tid][0], smax[tid][1]), fmaxf(smax[tid][2], smax[tid][3]));
        g_tmax[(size_t)(m0 + tid) * NTILES + blockIdx.x] = m;
    }
}

// ---------------- topk: tile-max guided selection + exact rescore ----------------
__global__ void __launch_bounds__(512) topk_kernel(const float* __restrict__ x,
                                                   const float* __restrict__ mean,
                                                   const float* __restrict__ stddev,
                                                   const float* __restrict__ outputs,
                                                   float* __restrict__ out) {
    int b = blockIdx.x, t = threadIdx.x;
    int lane = t & 31, warp = t >> 5;
    const float NI = neg_inf();
    int uni = g_flag;

    __shared__ int   s_tiles[TCAP];
    __shared__ int   s_nt, s_cnt;
    __shared__ int   sred[16];
    __shared__ uint32_t s_cand[NCAP];
    __shared__ float s_clp[NCAP];
    __shared__ float s_fv[TOPK];
    __shared__ int   s_fi[TOPK];
    __shared__ float s_w[TOPK];
    __shared__ float part[2 * 256];

    // ---- stage 1: tile-max threshold via block-vote binary search ----
    uint32_t tk = fkey(g_tmax[(size_t)b * NTILES + t]);
    uint32_t cur = 0;
    #pragma unroll 1
    for (int bit = 31; bit >= 0; --bit) {
        uint32_t T = cur | (1u << bit);
        int n = __syncthreads_count(tk >= T);
        if (n >= NCAND) cur = T;
    }
    if (t == 0) s_nt = 0;
    __syncthreads();
    if (tk >= cur) {
        int p = atomicAdd(&s_nt, 1);
        if (p < TCAP) s_tiles[p] = t;
    }
    __syncthreads();
    int ntl = s_nt < TCAP ? s_nt : TCAP;
    int total = ntl * 64;          // u32 words across selected tiles

    // ---- stage 2: gather selected tiles into registers as 16-bit keys ----
    const uint32_t* row32 = (const uint32_t*)(g_lh + (size_t)b * Kc);
    uint32_t u[16];
    #pragma unroll
    for (int i = 0; i < 16; i++) {
        int w = t + (i << 9);
        if (w < total) {
            int tile = s_tiles[w >> 6];
            u[i] = key2(row32[tile * 64 + (w & 63)]);
        } else {
            u[i] = 0x03FF03FFu;    // key of -inf in both halves
        }
    }

    // ---- stage 3: exact 16-bit threshold via block-sum binary search ----
    uint32_t cur16 = 0;
    #pragma unroll 1
    for (int bit = 15; bit >= 0; --bit) {
        uint32_t T = cur16 | (1u << bit);
        int c = 0;
        #pragma unroll
        for (int i = 0; i < 16; i++)
            c += ((u[i] & 0xFFFFu) >= T) + ((u[i] >> 16) >= T);
        #pragma unroll
        for (int off = 16; off > 0; off >>= 1)
            c += __shfl_xor_sync(0xffffffffu, c, off);
        __syncthreads();
        if (lane == 0) sred[warp] = c;
        __syncthreads();
        int n = 0;
        #pragma unroll
        for (int w = 0; w < 16; w++) n += sred[w];
        if (n >= NCAND) cur16 = T;
    }
    if (t == 0) s_cnt = 0;
    if (t < NCAP) s_clp[t] = NI;
    __syncthreads();

    // ---- stage 4: collect candidates ----
    #pragma unroll
    for (int i = 0; i < 16; i++) {
        int w = t + (i << 9);
        if (w < total) {
            uint32_t klo = u[i] & 0xFFFFu, khi = u[i] >> 16;
            uint32_t idx = (uint32_t)(s_tiles[w >> 6] * 128 + (w & 63) * 2);
            if (klo >= cur16) {
                int p = atomicAdd(&s_cnt, 1);
                if (p < NCAP) s_cand[p] = (klo << 16) | idx;
            }
            if (khi >= cur16) {
                int p = atomicAdd(&s_cnt, 1);
                if (p < NCAP) s_cand[p] = (khi << 16) | (idx + 1);
            }
        }
    }
    __syncthreads();
    int M = s_cnt < NCAP ? s_cnt : NCAP;

    // ---- exact fp32 rescore (one warp per candidate) ----
    for (int cc = warp; cc < M; cc += 16) {
        int c = (int)(s_cand[cc] & 0xFFFFu);
        float sq = 0.0f, sl = 0.0f;
        if (uni) {
            #pragma unroll
            for (int jj = 0; jj < 8; jj++) {
                int d = lane + (jj << 5);
                float m  = mean[(size_t)c * Dc + d];
                float xv = x[(size_t)b * Dc + d];
                float df = xv - m;
                sq = fmaf(df, df, sq);
            }
        } else {
            #pragma unroll
            for (int jj = 0; jj < 8; jj++) {
                int d = lane + (jj << 5);
                float m  = mean[(size_t)c * Dc + d];
                float sd = stddev[(size_t)c * Dc + d];
                float xv = x[(size_t)b * Dc + d];
                float iv = 1.0f / (sd * sd);
                float df = xv - m;
                sq = fmaf(df * df, iv, sq);
                sl += logf(sd);
            }
        }
        #pragma unroll
        for (int off = 16; off > 0; off >>= 1) {
            sq += __shfl_xor_sync(0xffffffffu, sq, off);
            sl += __shfl_xor_sync(0xffffffffu, sl, off);
        }
        if (lane == 0) s_clp[cc] = -0.5f * sq - sl - HALF_D_LOG2PI;
    }
    __syncthreads();

    // ---- exact top-32 of up to 96 rescored values (warp 0, 3 slots/lane) ----
    if (warp == 0) {
        float va[3]; int ia[3];
        #pragma unroll
        for (int q = 0; q < 3; q++) { ia[q] = lane + q * 32; va[q] = s_clp[ia[q]]; }
        for (int r = 0; r < TOPK; r++) {
            float m = va[0]; int mi = ia[0];
            if (va[1] > m) { m = va[1]; mi = ia[1]; }
            if (va[2] > m) { m = va[2]; mi = ia[2]; }
            float bm = m; int bi = mi;
            #pragma unroll
            for (int off = 16; off > 0; off >>= 1) {
                float ov = __shfl_down_sync(0xffffffffu, bm, off);
                int   oi = __shfl_down_sync(0xffffffffu, bi, off);
                if (ov > bm) { bm = ov; bi = oi; }
            }
            bm = __shfl_sync(0xffffffffu, bm, 0);
            bi = __shfl_sync(0xffffffffu, bi, 0);
            if (lane == 0) { s_fv[r] = bm; s_fi[r] = (int)(s_cand[bi] & 0xFFFFu); }
            #pragma unroll
            for (int q = 0; q < 3; q++) if (ia[q] == bi) va[q] = NI;
        }
    }
    __syncthreads();

    if (t < TOPK) {
        float e = expf(s_fv[t] - s_fv[0]);
        float s = e;
        #pragma unroll
        for (int off = 16; off > 0; off >>= 1)
            s += __shfl_xor_sync(0xffffffffu, s, off);
        s_w[t] = e / s;
    }
    __syncthreads();

    int o = t & 255, g = t >> 8;   // g in {0,1}
    float p = 0.0f;
    #pragma unroll
    for (int j = 0; j < 16; j++) {
        int jj = g * 16 + j;
        p = fmaf(s_w[jj], outputs[(size_t)s_fi[jj] * Oc + o], p);
    }
    part[g * 256 + o] = p;
    __syncthreads();
    if (t < 256)
        out[(size_t)b * Oc + t] = part[t] + part[256 + t];
}

// ---------------- launch ----------------
extern "C" void kernel_launch(void* const* d_in, const int* in_sizes, int n_in,
                              void* d_out, int out_size) {
    const float* x       = (const float*)d_in[0];
    const float* mean    = (const float*)d_in[1];
    const float* stddev  = (const float*)d_in[2];
    const float* outputs = (const float*)d_in[3];
    float* out = (float*)d_out;

    cudaFuncSetAttribute(gemm_kernel, cudaFuncAttributeMaxDynamicSharedMemorySize, GEMM_SMEM);

    prep_x_kernel<<<Bc, Dc>>>(x);
    prep_w_kernel<<<Kc, Dc>>>(mean, stddev);
    gemm_kernel<<<dim3(Kc / 128, Bc / 128), 256, GEMM_SMEM>>>();
    topk_kernel<<<Bc, 512>>>(x, mean, stddev, outputs, out);
}